// round 11
// baseline (speedup 1.0000x reference)
#include <cuda_runtime.h>
#include <cuda_bf16.h>
#include <cstdint>

#define NB   64
#define TT   12
#define NN   325
#define HH   64
#define EE   32
#define LHH  128
#define NOUT 12
#define XST  97
#define MOFF 65

#define MROWS 64
#define NCHUNK 6                 // ceil(325/64)
#define NKT   5                  // k-tiles of 16 over augmented K=80

typedef unsigned long long ull;

// ---------------- device scratch ----------------
__device__ float g_meta[NB * EE];
__device__ float g_hidden[3 * 4 * NB * LHH];
__device__ float g_Wx[4 * NB * HH];
__device__ float g_bg[4 * NB * HH];
__device__ __align__(16) ulonglong2 g_WB[NB * 4 * 1024];    // dense kt 0..3 frags
__device__ __align__(16) ulonglong2 g_WBaug[NB * 256];      // compact kt=4 frags

// ---------------- activations ----------------
__device__ __forceinline__ float ex2f(float x) {
    float y; asm("ex2.approx.f32 %0,%1;" : "=f"(y) : "f"(x)); return y;
}
__device__ __forceinline__ float rcpf(float x) {
    float y; asm("rcp.approx.f32 %0,%1;" : "=f"(y) : "f"(x)); return y;
}
__device__ __forceinline__ float sig_a(float z) {
    return rcpf(1.0f + ex2f(-1.4426950408889634f * z));
}
__device__ __forceinline__ float tanh_a(float z) {
    return fmaf(-2.0f, rcpf(1.0f + ex2f(2.8853900817779268f * z)), 1.0f);
}

// ---------------- mma.sync m16n8k16 bf16 ----------------
__device__ __forceinline__ void mma16816(float* c,
    uint32_t a0, uint32_t a1, uint32_t a2, uint32_t a3,
    uint32_t b0, uint32_t b1) {
    asm volatile(
        "mma.sync.aligned.m16n8k16.row.col.f32.bf16.bf16.f32 "
        "{%0,%1,%2,%3}, {%4,%5,%6,%7}, {%8,%9}, {%0,%1,%2,%3};"
        : "+f"(c[0]), "+f"(c[1]), "+f"(c[2]), "+f"(c[3])
        : "r"(a0), "r"(a1), "r"(a2), "r"(a3), "r"(b0), "r"(b1));
}
__device__ __forceinline__ uint32_t lo32(ull v) { return (uint32_t)v; }
__device__ __forceinline__ uint32_t hi32(ull v) { return (uint32_t)(v >> 32); }
__device__ __forceinline__ uint32_t pkbf(float a, float b) {
    __nv_bfloat16 ha = __float2bfloat16_rn(a);
    __nv_bfloat16 hb = __float2bfloat16_rn(b);
    return (uint32_t)__bfloat16_as_ushort(ha) |
           ((uint32_t)__bfloat16_as_ushort(hb) << 16);
}
// pack 4 floats into {hi64, lo64} fragment words
__device__ __forceinline__ ulonglong2 pkfrag(float v00, float v01, float v10, float v11) {
    __nv_bfloat16 h00 = __float2bfloat16_rn(v00);
    __nv_bfloat16 h01 = __float2bfloat16_rn(v01);
    __nv_bfloat16 h10 = __float2bfloat16_rn(v10);
    __nv_bfloat16 h11 = __float2bfloat16_rn(v11);
    uint32_t p0 = (uint32_t)__bfloat16_as_ushort(h00) |
                  ((uint32_t)__bfloat16_as_ushort(h01) << 16);
    uint32_t p1 = (uint32_t)__bfloat16_as_ushort(h10) |
                  ((uint32_t)__bfloat16_as_ushort(h11) << 16);
    uint32_t q0 = pkbf(v00 - __bfloat162float(h00), v01 - __bfloat162float(h01));
    uint32_t q1 = pkbf(v10 - __bfloat162float(h10), v11 - __bfloat162float(h11));
    ulonglong2 w;
    w.x = (ull)p0 | ((ull)p1 << 32);
    w.y = (ull)q0 | ((ull)q1 << 32);
    return w;
}

// ---------------- K1: meta ----------------
__global__ void k_meta(const float* __restrict__ x) {
    int b = blockIdx.x, e = threadIdx.x;
    float s = 0.f;
    #pragma unroll
    for (int t = 0; t < TT; t++)
        s += x[((size_t)(b * TT + t) * NN) * XST + MOFF + e];
    g_meta[b * EE + e] = s * (1.0f / TT);
}

// ---------------- K2: first MLP layers ----------------
__global__ void k_hidden(const float* __restrict__ xW1, const float* __restrict__ xb1,
                         const float* __restrict__ hW1, const float* __restrict__ hb1,
                         const float* __restrict__ bW1, const float* __restrict__ bb1) {
    int b = blockIdx.x, g = blockIdx.y, m = blockIdx.z;
    int l = threadIdx.x;
    const float* W1 = (m == 0) ? xW1 : (m == 1) ? hW1 : bW1;
    const float* b1 = (m == 0) ? xb1 : (m == 1) ? hb1 : bb1;
    float acc = b1[g * LHH + l];
    #pragma unroll 8
    for (int e = 0; e < EE; e++)
        acc = fmaf(g_meta[b * EE + e], W1[(g * EE + e) * LHH + l], acc);
    g_hidden[((m * 4 + g) * NB + b) * LHH + l] = fmaxf(acc, 0.f);
}

// ---------------- K3ab: Wx / bias second layers ----------------
__global__ void k_small2(const float* __restrict__ xW2, const float* __restrict__ xb2,
                         const float* __restrict__ bW2, const float* __restrict__ bb2) {
    int b = blockIdx.x, g = blockIdx.y, m2 = blockIdx.z;
    int k = threadIdx.x;
    int m = (m2 == 0) ? 0 : 2;
    const float* W2 = (m2 == 0) ? xW2 : bW2;
    const float* b2 = (m2 == 0) ? xb2 : bb2;
    const float* hid = &g_hidden[((m * 4 + g) * NB + b) * LHH];
    float acc = b2[g * HH + k];
    #pragma unroll 8
    for (int l = 0; l < LHH; l++)
        acc = fmaf(hid[l], W2[(g * LHH + l) * HH + k], acc);
    float* dst = (m2 == 0) ? g_Wx : g_bg;
    dst[(g * NB + b) * HH + k] = acc;
}

// ---------------- K3c: fused Wh GEMM + fragment pack ----------------
// CTA (jt=kt 0..3, g 0..3, bt 0..7): computes Wh[g][b][j][kk] for
// j in [16kt,16kt+16), kk 0..63, 8 batches, then emits B fragments.
__global__ __launch_bounds__(256)
void k_whfrag(const float* __restrict__ hW2, const float* __restrict__ hb2) {
    __shared__ float hs[8][LHH];
    __shared__ float whs[8][64][17];          // [b][kk][j] padded
    int jt = blockIdx.x, g = blockIdx.y, bt = blockIdx.z;
    int tid = threadIdx.x;

    for (int i = tid; i < 8 * LHH; i += 256)
        hs[i >> 7][i & 127] =
            g_hidden[((4 + g) * NB + bt * 8 + (i >> 7)) * LHH + (i & 127)];
    __syncthreads();

    int jq = tid >> 6;        // 0..3  (j group of 4)
    int kk = tid & 63;
    float acc[4][8];
    #pragma unroll
    for (int jl = 0; jl < 4; jl++)
        #pragma unroll
        for (int bb = 0; bb < 8; bb++) acc[jl][bb] = 0.f;

    const float* wp = hW2 + (size_t)(g * LHH) * 4096 + (jt * 16 + jq * 4) * 64 + kk;
    #pragma unroll 2
    for (int l = 0; l < LHH; l++) {
        float w0 = wp[0], w1 = wp[64], w2 = wp[128], w3 = wp[192];
        wp += 4096;
        #pragma unroll
        for (int bb = 0; bb < 8; bb++) {
            float h = hs[bb][l];
            acc[0][bb] = fmaf(h, w0, acc[0][bb]);
            acc[1][bb] = fmaf(h, w1, acc[1][bb]);
            acc[2][bb] = fmaf(h, w2, acc[2][bb]);
            acc[3][bb] = fmaf(h, w3, acc[3][bb]);
        }
    }
    #pragma unroll
    for (int jl = 0; jl < 4; jl++) {
        float bias = hb2[g * 4096 + (jt * 16 + jq * 4 + jl) * 64 + kk];
        #pragma unroll
        for (int bb = 0; bb < 8; bb++)
            whs[bb][kk][jq * 4 + jl] = acc[jl][bb] + bias;
    }
    __syncthreads();

    // fragment emit: thread owns (ntgl, L), loops over 8 batches
    int ntgl = tid >> 5, L = tid & 31;
    int kk2 = ntgl * 8 + (L >> 2);
    int j0 = (L & 3) * 2;
    #pragma unroll
    for (int bb = 0; bb < 8; bb++) {
        ulonglong2 w = pkfrag(whs[bb][kk2][j0],     whs[bb][kk2][j0 + 1],
                              whs[bb][kk2][j0 + 8], whs[bb][kk2][j0 + 9]);
        g_WB[(size_t)(bt * 8 + bb) * 4096 + jt * 1024 + (g * 8 + ntgl) * 32 + L] = w;
    }
}

// ---------------- K3d: compact augmented tile (Wx, bias) ----------------
__global__ void k_packaug() {
    int b = blockIdx.x, tid = threadIdx.x;   // 256 = ntg*8 + Lq
    int ntg = tid >> 3, Lq = tid & 7;
    int g = ntg >> 3, kk = (ntg & 7) * 8 + Lq;
    float wx = g_Wx[(g * NB + b) * HH + kk];
    float bg = g_bg[(g * NB + b) * HH + kk];
    __nv_bfloat16 wh = __float2bfloat16_rn(wx);
    __nv_bfloat16 bh = __float2bfloat16_rn(bg);
    uint32_t p0 = (uint32_t)__bfloat16_as_ushort(wh) |
                  ((uint32_t)__bfloat16_as_ushort(bh) << 16);
    uint32_t q0 = pkbf(wx - __bfloat162float(wh), bg - __bfloat162float(bh));
    ulonglong2 w;
    w.x = (ull)p0;
    w.y = (ull)q0;
    g_WBaug[b * 256 + tid] = w;
}

// ---------------- K4: HMMA LSTM recurrence + FC head ----------------
// smem byte offsets
#define SM_WB   0        // 4*1024 ulonglong2 = 65536  (hF 16KB overlays after)
#define SM_AUG  65536    // 256 ulonglong2 = 4096
#define SM_AH   69632    // 4mt*5kt*32 ulonglong2 = 10240 (FC overlay after loop)
#define SM_AL   79872    // 10240
#define SM_XS   90112    // 64*12*4 = 3072
#define SM_F1B  93184    // 128
#define SM_F2B  93312    // 64
#define SM_MID  93376    // 1024
#define SM_TOT  94400
#define SM_FC1  SM_AH            // overlay (post-loop)
#define SM_FC2  (SM_AH + 8192)   // overlay

__global__ __launch_bounds__(256, 2)
void k_lstm3(const float* __restrict__ x,
             const float* __restrict__ fc1W, const float* __restrict__ fc1b,
             const float* __restrict__ fc2W, const float* __restrict__ fc2b,
             float* __restrict__ out) {
    extern __shared__ char smc[];
    ulonglong2* WB   = (ulonglong2*)(smc + SM_WB);
    ulonglong2* WBau = (ulonglong2*)(smc + SM_AUG);
    ulonglong2* AH2  = (ulonglong2*)(smc + SM_AH);
    ulonglong2* AL2  = (ulonglong2*)(smc + SM_AL);
    float* xs   = (float*)(smc + SM_XS);
    float* f1bs = (float*)(smc + SM_F1B);
    float* f2bs = (float*)(smc + SM_F2B);
    float* mids = (float*)(smc + SM_MID);
    float* hF   = (float*)(smc + SM_WB);    // overlay

    int chunk = blockIdx.x, b = blockIdx.y;
    int tid = threadIdx.x;
    int w = tid >> 5, L = tid & 31;
    int mt = w >> 1, half = w & 1;
    int n0 = chunk * MROWS;
    int r0 = mt * 16 + (L >> 2);            // chunk-local row (slot 0); slot1 = +8

    // ---- stage ----
    {
        const uint4* src = (const uint4*)&g_WB[(size_t)b * 4096];
        uint4* dst = (uint4*)WB;
        for (int i = tid; i < 4096; i += 256) dst[i] = src[i];
        if (tid < 256) ((uint4*)WBau)[tid] = ((const uint4*)&g_WBaug[b * 256])[tid];
    }
    for (int i = tid; i < 2 * 4 * NKT * 32; i += 256) {
        ulonglong2 z; z.x = 0ull; z.y = 0ull;
        AH2[i] = z;                          // covers AH2 then AL2 (contiguous)
    }
    for (int i = tid; i < MROWS * TT; i += 256) {
        int r = i / TT, t = i % TT;
        int n = n0 + r;
        xs[r * TT + t] = (n < NN) ? x[((size_t)(b * TT + t) * NN + n) * XST] : 0.f;
    }
    if (tid < 32) f1bs[tid] = fc1b[tid];
    if (tid < NOUT) f2bs[tid] = fc2b[tid];
    __syncthreads();

    // seed augmented kt=4 A tile with (x_0, 1.0); half==0 warps cover both slots
    if (half == 0 && (L & 3) == 0) {
        ull* aw = (ull*)&AH2[(mt * NKT + 4) * 32 + L];
        ull* al = (ull*)&AL2[(mt * NKT + 4) * 32 + L];
        #pragma unroll
        for (int s = 0; s < 2; s++) {
            float xv = xs[(r0 + s * 8) * TT];
            __nv_bfloat16 xh = __float2bfloat16_rn(xv);
            aw[s] = (ull)((uint32_t)__bfloat16_as_ushort(xh) | (0x3F80u << 16));
            al[s] = (ull)pkbf(xv - __bfloat162float(xh), 0.f);
        }
    }

    const bool augok = ((L & 3) == 0);
    const int Lq = L >> 2;

    float cst[16];
    #pragma unroll
    for (int i = 0; i < 16; i++) cst[i] = 0.f;

    for (int t = 0; t < TT; t++) {
        __syncthreads();                     // A frags (h_{t-1}, x_t) visible

        float acc[4][4][4];
        #pragma unroll
        for (int g = 0; g < 4; g++)
            #pragma unroll
            for (int nl = 0; nl < 4; nl++)
                #pragma unroll
                for (int i = 0; i < 4; i++) acc[g][nl][i] = 0.f;

        #pragma unroll
        for (int kt = 0; kt < NKT; kt++) {
            if (t == 0 && kt < 4) continue;  // h=0 at t=0
            ulonglong2 ah = AH2[(mt * NKT + kt) * 32 + L];
            ulonglong2 al = AL2[(mt * NKT + kt) * 32 + L];
            uint32_t a0h = lo32(ah.x), a2h = hi32(ah.x);
            uint32_t a1h = lo32(ah.y), a3h = hi32(ah.y);
            uint32_t a0l = lo32(al.x), a2l = hi32(al.x);
            uint32_t a1l = lo32(al.y), a3l = hi32(al.y);
            #pragma unroll
            for (int g = 0; g < 4; g++) {
                #pragma unroll
                for (int nl = 0; nl < 4; nl++) {
                    int ntg = g * 8 + half * 4 + nl;
                    ulonglong2 bw;
                    if (kt < 4) {
                        bw = WB[(kt * 32 + ntg) * 32 + L];
                    } else if (augok) {
                        bw = WBau[ntg * 8 + Lq];
                    } else {
                        bw.x = 0ull; bw.y = 0ull;
                    }
                    mma16816(acc[g][nl], a0h, a1h, a2h, a3h, lo32(bw.x), hi32(bw.x));
                    mma16816(acc[g][nl], a0h, a1h, a2h, a3h, lo32(bw.y), hi32(bw.y));
                    mma16816(acc[g][nl], a0l, a1l, a2l, a3l, lo32(bw.x), hi32(bw.x));
                }
            }
        }
        __syncthreads();                     // all A/B reads done before rewrites

        // elementwise: this lane owns all 4 gates for 2 rows x 8 k-cols
        float hv[4][2][2];                   // [nl][s][q]
        #pragma unroll
        for (int nl = 0; nl < 4; nl++)
            #pragma unroll
            for (int s = 0; s < 2; s++)
                #pragma unroll
                for (int q = 0; q < 2; q++) {
                    int ci = s * 2 + q;
                    float zg = acc[0][nl][ci];
                    float zi = acc[1][nl][ci];
                    float zf = acc[2][nl][ci];
                    float zo = acc[3][nl][ci];
                    int cix = nl * 4 + ci;
                    float cv = fmaf(cst[cix], sig_a(zf), tanh_a(zg) * sig_a(zi));
                    cst[cix] = cv;
                    hv[nl][s][q] = tanh_a(cv) * sig_a(zo);
                }

        if (t == TT - 1) {
            #pragma unroll
            for (int nl = 0; nl < 4; nl++)
                #pragma unroll
                for (int s = 0; s < 2; s++)
                    #pragma unroll
                    for (int q = 0; q < 2; q++) {
                        int k = half * 32 + nl * 8 + (L & 3) * 2 + q;
                        hF[k * MROWS + r0 + s * 8] = hv[nl][s][q];
                    }
        } else {
            // write A fragments for t+1 (this warp owns kt = 2*half, 2*half+1)
            #pragma unroll
            for (int ktl = 0; ktl < 2; ktl++) {
                int kt = 2 * half + ktl;
                ull* aw = (ull*)&AH2[(mt * NKT + kt) * 32 + L];
                ull* al = (ull*)&AL2[(mt * NKT + kt) * 32 + L];
                #pragma unroll
                for (int s = 0; s < 2; s++) {
                    float e0 = hv[2 * ktl][s][0],     e1 = hv[2 * ktl][s][1];
                    float o0 = hv[2 * ktl + 1][s][0], o1 = hv[2 * ktl + 1][s][1];
                    uint32_t phE = pkbf(e0, e1), phO = pkbf(o0, o1);
                    aw[s] = (ull)phE | ((ull)phO << 32);
                    __nv_bfloat16 be0 = __float2bfloat16_rn(e0);
                    __nv_bfloat16 be1 = __float2bfloat16_rn(e1);
                    __nv_bfloat16 bo0 = __float2bfloat16_rn(o0);
                    __nv_bfloat16 bo1 = __float2bfloat16_rn(o1);
                    uint32_t plE = pkbf(e0 - __bfloat162float(be0), e1 - __bfloat162float(be1));
                    uint32_t plO = pkbf(o0 - __bfloat162float(bo0), o1 - __bfloat162float(bo1));
                    al[s] = (ull)plE | ((ull)plO << 32);
                }
            }
            if (half == 0 && (L & 3) == 0) {  // x_{t+1} augment
                ull* aw = (ull*)&AH2[(mt * NKT + 4) * 32 + L];
                ull* al = (ull*)&AL2[(mt * NKT + 4) * 32 + L];
                #pragma unroll
                for (int s = 0; s < 2; s++) {
                    float xv = xs[(r0 + s * 8) * TT + t + 1];
                    __nv_bfloat16 xh = __float2bfloat16_rn(xv);
                    aw[s] = (ull)((uint32_t)__bfloat16_as_ushort(xh) | (0x3F80u << 16));
                    al[s] = (ull)pkbf(xv - __bfloat162float(xh), 0.f);
                }
            }
        }
    }
    __syncthreads();

    // ---- load FC weights into overlay (A frags dead now) ----
    float* fc1s = (float*)(smc + SM_FC1);
    float* fc2s = (float*)(smc + SM_FC2);
    for (int i = tid; i < HH * 32; i += 256) fc1s[i] = fc1W[i];
    for (int i = tid; i < 32 * NOUT; i += 256) fc2s[i] = fc2W[i];
    __syncthreads();

    // ---- FC head: relu(h) -> 32 relu -> 12 ----
    #pragma unroll
    for (int rr = 0; rr < 8; rr++) {
        int row = w * 8 + rr;
        int n = n0 + row;
        float m = f1bs[L];
        #pragma unroll 8
        for (int j = 0; j < HH; j++)
            m = fmaf(fmaxf(hF[j * MROWS + row], 0.f), fc1s[j * 32 + L], m);
        m = fmaxf(m, 0.f);
        mids[w * 32 + L] = m;
        __syncwarp();
        if (L < NOUT) {
            float o = f2bs[L];
            #pragma unroll
            for (int q = 0; q < 32; q++)
                o = fmaf(mids[w * 32 + q], fc2s[q * NOUT + L], o);
            if (n < NN) out[(b * NOUT + L) * NN + n] = o;
        }
        __syncwarp();
    }
}

// ---------------- launch ----------------
extern "C" void kernel_launch(void* const* d_in, const int* in_sizes, int n_in,
                              void* d_out, int out_size) {
    const float* x      = (const float*)d_in[0];
    const float* lwx_W1 = (const float*)d_in[1];
    const float* lwx_b1 = (const float*)d_in[2];
    const float* lwx_W2 = (const float*)d_in[3];
    const float* lwx_b2 = (const float*)d_in[4];
    const float* lwh_W1 = (const float*)d_in[5];
    const float* lwh_b1 = (const float*)d_in[6];
    const float* lwh_W2 = (const float*)d_in[7];
    const float* lwh_b2 = (const float*)d_in[8];
    const float* lb_W1  = (const float*)d_in[9];
    const float* lb_b1  = (const float*)d_in[10];
    const float* lb_W2  = (const float*)d_in[11];
    const float* lb_b2  = (const float*)d_in[12];
    const float* fc1_W  = (const float*)d_in[13];
    const float* fc1_b  = (const float*)d_in[14];
    const float* fc2_W  = (const float*)d_in[15];
    const float* fc2_b  = (const float*)d_in[16];
    float* out = (float*)d_out;

    cudaFuncSetAttribute(k_lstm3, cudaFuncAttributeMaxDynamicSharedMemorySize, SM_TOT);

    k_meta<<<NB, EE>>>(x);
    k_hidden<<<dim3(NB, 4, 3), LHH>>>(lwx_W1, lwx_b1, lwh_W1, lwh_b1, lb_W1, lb_b1);
    k_small2<<<dim3(NB, 4, 2), HH>>>(lwx_W2, lwx_b2, lb_W2, lb_b2);
    k_whfrag<<<dim3(4, 4, 8), 256>>>(lwh_W2, lwh_b2);
    k_packaug<<<NB, 256>>>();
    k_lstm3<<<dim3(NCHUNK, NB), 256, SM_TOT>>>(x, fc1_W, fc1_b, fc2_W, fc2_b, out);
}

// round 15
// speedup vs baseline: 1.0729x; 1.0729x over previous
#include <cuda_runtime.h>
#include <cuda_bf16.h>
#include <cstdint>

#define NB   64
#define TT   12
#define NN   325
#define HH   64
#define EE   32
#define LHH  128
#define NOUT 12
#define XST  97
#define MOFF 65

#define MROWS 64
#define NCHUNK 6                 // ceil(325/64)
#define NKT   5                  // k-tiles of 16 over augmented K=80

typedef unsigned long long ull;

// ---------------- device scratch ----------------
__device__ float g_meta[NB * EE];
__device__ float g_hidden[3 * 4 * NB * LHH];
__device__ float g_Wx[4 * NB * HH];
__device__ float g_bg[4 * NB * HH];
__device__ float g_Wh[4 * NB * HH * HH];
__device__ __align__(16) ulonglong2 g_WB[NB * 4 * 1024];    // dense kt 0..3 frags
__device__ __align__(16) ulonglong2 g_WBaug[NB * 256];      // compact kt=4 frags

// ---------------- activations ----------------
__device__ __forceinline__ float ex2f(float x) {
    float y; asm("ex2.approx.f32 %0,%1;" : "=f"(y) : "f"(x)); return y;
}
__device__ __forceinline__ float rcpf(float x) {
    float y; asm("rcp.approx.f32 %0,%1;" : "=f"(y) : "f"(x)); return y;
}
__device__ __forceinline__ float sig_a(float z) {
    return rcpf(1.0f + ex2f(-1.4426950408889634f * z));
}
__device__ __forceinline__ float tanh_a(float z) {
    return fmaf(-2.0f, rcpf(1.0f + ex2f(2.8853900817779268f * z)), 1.0f);
}

// ---------------- mma.sync m16n8k16 bf16 ----------------
__device__ __forceinline__ void mma16816(float* c,
    uint32_t a0, uint32_t a1, uint32_t a2, uint32_t a3,
    uint32_t b0, uint32_t b1) {
    asm volatile(
        "mma.sync.aligned.m16n8k16.row.col.f32.bf16.bf16.f32 "
        "{%0,%1,%2,%3}, {%4,%5,%6,%7}, {%8,%9}, {%0,%1,%2,%3};"
        : "+f"(c[0]), "+f"(c[1]), "+f"(c[2]), "+f"(c[3])
        : "r"(a0), "r"(a1), "r"(a2), "r"(a3), "r"(b0), "r"(b1));
}
__device__ __forceinline__ uint32_t lo32(ull v) { return (uint32_t)v; }
__device__ __forceinline__ uint32_t hi32(ull v) { return (uint32_t)(v >> 32); }
__device__ __forceinline__ uint32_t pkbf(float a, float b) {
    __nv_bfloat16 ha = __float2bfloat16_rn(a);
    __nv_bfloat16 hb = __float2bfloat16_rn(b);
    return (uint32_t)__bfloat16_as_ushort(ha) |
           ((uint32_t)__bfloat16_as_ushort(hb) << 16);
}

// ---------------- K1: meta ----------------
__global__ void k_meta(const float* __restrict__ x) {
    int b = blockIdx.x, e = threadIdx.x;
    float s = 0.f;
    #pragma unroll
    for (int t = 0; t < TT; t++)
        s += x[((size_t)(b * TT + t) * NN) * XST + MOFF + e];
    g_meta[b * EE + e] = s * (1.0f / TT);
}

// ---------------- K2: first MLP layers ----------------
__global__ void k_hidden(const float* __restrict__ xW1, const float* __restrict__ xb1,
                         const float* __restrict__ hW1, const float* __restrict__ hb1,
                         const float* __restrict__ bW1, const float* __restrict__ bb1) {
    int b = blockIdx.x, g = blockIdx.y, m = blockIdx.z;
    int l = threadIdx.x;
    const float* W1 = (m == 0) ? xW1 : (m == 1) ? hW1 : bW1;
    const float* b1 = (m == 0) ? xb1 : (m == 1) ? hb1 : bb1;
    float acc = b1[g * LHH + l];
    #pragma unroll 8
    for (int e = 0; e < EE; e++)
        acc = fmaf(g_meta[b * EE + e], W1[(g * EE + e) * LHH + l], acc);
    g_hidden[((m * 4 + g) * NB + b) * LHH + l] = fmaxf(acc, 0.f);
}

// ---------------- K3ab: Wx / bias second layers ----------------
__global__ void k_small2(const float* __restrict__ xW2, const float* __restrict__ xb2,
                         const float* __restrict__ bW2, const float* __restrict__ bb2) {
    int b = blockIdx.x, g = blockIdx.y, m2 = blockIdx.z;
    int k = threadIdx.x;
    int m = (m2 == 0) ? 0 : 2;
    const float* W2 = (m2 == 0) ? xW2 : bW2;
    const float* b2 = (m2 == 0) ? xb2 : bb2;
    const float* hid = &g_hidden[((m * 4 + g) * NB + b) * LHH];
    float acc = b2[g * HH + k];
    #pragma unroll 8
    for (int l = 0; l < LHH; l++)
        acc = fmaf(hid[l], W2[(g * LHH + l) * HH + k], acc);
    float* dst = (m2 == 0) ? g_Wx : g_bg;
    dst[(g * NB + b) * HH + k] = acc;
}

// ---------------- K3c: Wh second layer GEMM (512 CTAs, proven) ----------
__global__ void k_wh2(const float* __restrict__ hW2, const float* __restrict__ hb2) {
    __shared__ float hs[4][LHH];
    int kq = blockIdx.x, bt = blockIdx.y, g = blockIdx.z;
    int tid = threadIdx.x;                   // 256
    for (int i = tid; i < 4 * LHH; i += 256)
        hs[i >> 7][i & 127] = g_hidden[((4 + g) * NB + bt * 4 + (i >> 7)) * LHH + (i & 127)];
    __syncthreads();
    int k2 = kq * 512 + tid * 2;
    float2 acc[4];
    #pragma unroll
    for (int bb = 0; bb < 4; bb++) acc[bb] = make_float2(0.f, 0.f);
    #pragma unroll 8
    for (int l = 0; l < LHH; l++) {
        float2 wv = *(const float2*)&hW2[(size_t)(g * LHH + l) * 4096 + k2];
        #pragma unroll
        for (int bb = 0; bb < 4; bb++) {
            float h = hs[bb][l];
            acc[bb].x = fmaf(h, wv.x, acc[bb].x);
            acc[bb].y = fmaf(h, wv.y, acc[bb].y);
        }
    }
    float2 bias = *(const float2*)&hb2[g * 4096 + k2];
    #pragma unroll
    for (int bb = 0; bb < 4; bb++) {
        float2 v = make_float2(acc[bb].x + bias.x, acc[bb].y + bias.y);
        *(float2*)&g_Wh[(size_t)(g * NB + bt * 4 + bb) * 4096 + k2] = v;
    }
}

// ---------------- K3d: pack dense Wh fragments (kt 0..3) ----------------
__global__ void k_pack3() {
    int b = blockIdx.x, kt = blockIdx.y, tid = threadIdx.x;
    for (int i = tid; i < 1024; i += 256) {
        int L = i & 31, ntg = i >> 5;
        int g = ntg >> 3, kk = (ntg & 7) * 8 + (L >> 2);
        int j0 = kt * 16 + (L & 3) * 2;
        const float* src = &g_Wh[((size_t)(g * NB + b) << 12) + kk];
        float v00 = src[(size_t)j0 * 64];
        float v01 = src[(size_t)(j0 + 1) * 64];
        float v10 = src[(size_t)(j0 + 8) * 64];
        float v11 = src[(size_t)(j0 + 9) * 64];
        __nv_bfloat16 h00 = __float2bfloat16_rn(v00);
        __nv_bfloat16 h01 = __float2bfloat16_rn(v01);
        __nv_bfloat16 h10 = __float2bfloat16_rn(v10);
        __nv_bfloat16 h11 = __float2bfloat16_rn(v11);
        uint32_t p0 = (uint32_t)__bfloat16_as_ushort(h00) |
                      ((uint32_t)__bfloat16_as_ushort(h01) << 16);
        uint32_t p1 = (uint32_t)__bfloat16_as_ushort(h10) |
                      ((uint32_t)__bfloat16_as_ushort(h11) << 16);
        uint32_t q0 = pkbf(v00 - __bfloat162float(h00), v01 - __bfloat162float(h01));
        uint32_t q1 = pkbf(v10 - __bfloat162float(h10), v11 - __bfloat162float(h11));
        ulonglong2 w;
        w.x = (ull)p0 | ((ull)p1 << 32);
        w.y = (ull)q0 | ((ull)q1 << 32);
        g_WB[(size_t)b * 4096 + kt * 1024 + i] = w;
    }
}

// ---------------- K3e: compact augmented tile (Wx, bias) ----------------
__global__ void k_packaug() {
    int b = blockIdx.x, tid = threadIdx.x;   // 256 = ntg*8 + Lq
    int ntg = tid >> 3, Lq = tid & 7;
    int g = ntg >> 3, kk = (ntg & 7) * 8 + Lq;
    float wx = g_Wx[(g * NB + b) * HH + kk];
    float bg = g_bg[(g * NB + b) * HH + kk];
    __nv_bfloat16 wh = __float2bfloat16_rn(wx);
    __nv_bfloat16 bh = __float2bfloat16_rn(bg);
    uint32_t p0 = (uint32_t)__bfloat16_as_ushort(wh) |
                  ((uint32_t)__bfloat16_as_ushort(bh) << 16);
    uint32_t q0 = pkbf(wx - __bfloat162float(wh), bg - __bfloat162float(bh));
    ulonglong2 w;
    w.x = (ull)p0;
    w.y = (ull)q0;
    g_WBaug[b * 256 + tid] = w;
}

// ---------------- K4: HMMA LSTM recurrence + FC head ----------------
// smem byte offsets
#define SM_WB   0        // 4*1024 ulonglong2 = 65536  (hF 16KB overlays after)
#define SM_AUG  65536    // 256 ulonglong2 = 4096
#define SM_AH   69632    // 4mt*5kt*32 ulonglong2 = 10240 (FC overlay after loop)
#define SM_AL   79872    // 10240
#define SM_XS   90112    // 64*12*4 = 3072
#define SM_F1B  93184    // 128
#define SM_F2B  93312    // 64
#define SM_MID  93376    // 1024
#define SM_TOT  94400
#define SM_FC1  SM_AH            // overlay (post-loop)
#define SM_FC2  (SM_AH + 8192)   // overlay

__global__ __launch_bounds__(256, 2)
void k_lstm3(const float* __restrict__ x,
             const float* __restrict__ fc1W, const float* __restrict__ fc1b,
             const float* __restrict__ fc2W, const float* __restrict__ fc2b,
             float* __restrict__ out) {
    extern __shared__ char smc[];
    ulonglong2* WB   = (ulonglong2*)(smc + SM_WB);
    ulonglong2* WBau = (ulonglong2*)(smc + SM_AUG);
    ulonglong2* AH2  = (ulonglong2*)(smc + SM_AH);
    ulonglong2* AL2  = (ulonglong2*)(smc + SM_AL);
    float* xs   = (float*)(smc + SM_XS);
    float* f1bs = (float*)(smc + SM_F1B);
    float* f2bs = (float*)(smc + SM_F2B);
    float* mids = (float*)(smc + SM_MID);
    float* hF   = (float*)(smc + SM_WB);    // overlay

    int chunk = blockIdx.x, b = blockIdx.y;
    int tid = threadIdx.x;
    int w = tid >> 5, L = tid & 31;
    int mt = w >> 1, half = w & 1;
    int n0 = chunk * MROWS;
    int r0 = mt * 16 + (L >> 2);            // chunk-local row (slot 0); slot1 = +8

    // ---- stage ----
    {
        const uint4* src = (const uint4*)&g_WB[(size_t)b * 4096];
        uint4* dst = (uint4*)WB;
        for (int i = tid; i < 4096; i += 256) dst[i] = src[i];
        if (tid < 256) ((uint4*)WBau)[tid] = ((const uint4*)&g_WBaug[b * 256])[tid];
    }
    for (int i = tid; i < 2 * 4 * NKT * 32; i += 256) {
        ulonglong2 z; z.x = 0ull; z.y = 0ull;
        AH2[i] = z;                          // covers AH2 then AL2 (contiguous)
    }
    for (int i = tid; i < MROWS * TT; i += 256) {
        int r = i / TT, t = i % TT;
        int n = n0 + r;
        xs[r * TT + t] = (n < NN) ? x[((size_t)(b * TT + t) * NN + n) * XST] : 0.f;
    }
    if (tid < 32) f1bs[tid] = fc1b[tid];
    if (tid < NOUT) f2bs[tid] = fc2b[tid];
    __syncthreads();

    // seed augmented kt=4 A tile with (x_0, 1.0); half==0 warps cover both slots
    if (half == 0 && (L & 3) == 0) {
        ull* aw = (ull*)&AH2[(mt * NKT + 4) * 32 + L];
        ull* al = (ull*)&AL2[(mt * NKT + 4) * 32 + L];
        #pragma unroll
        for (int s = 0; s < 2; s++) {
            float xv = xs[(r0 + s * 8) * TT];
            __nv_bfloat16 xh = __float2bfloat16_rn(xv);
            aw[s] = (ull)((uint32_t)__bfloat16_as_ushort(xh) | (0x3F80u << 16));
            al[s] = (ull)pkbf(xv - __bfloat162float(xh), 0.f);
        }
    }

    const bool augok = ((L & 3) == 0);
    const int Lq = L >> 2;

    float cst[16];
    #pragma unroll
    for (int i = 0; i < 16; i++) cst[i] = 0.f;

    for (int t = 0; t < TT; t++) {
        __syncthreads();                     // A frags (h_{t-1}, x_t) visible

        float acc[4][4][4];
        #pragma unroll
        for (int g = 0; g < 4; g++)
            #pragma unroll
            for (int nl = 0; nl < 4; nl++)
                #pragma unroll
                for (int i = 0; i < 4; i++) acc[g][nl][i] = 0.f;

        #pragma unroll
        for (int kt = 0; kt < NKT; kt++) {
            if (t == 0 && kt < 4) continue;  // h=0 at t=0
            ulonglong2 ah = AH2[(mt * NKT + kt) * 32 + L];
            ulonglong2 al = AL2[(mt * NKT + kt) * 32 + L];
            uint32_t a0h = lo32(ah.x), a2h = hi32(ah.x);
            uint32_t a1h = lo32(ah.y), a3h = hi32(ah.y);
            uint32_t a0l = lo32(al.x), a2l = hi32(al.x);
            uint32_t a1l = lo32(al.y), a3l = hi32(al.y);
            #pragma unroll
            for (int g = 0; g < 4; g++) {
                #pragma unroll
                for (int nl = 0; nl < 4; nl++) {
                    int ntg = g * 8 + half * 4 + nl;
                    ulonglong2 bw;
                    if (kt < 4) {
                        bw = WB[(kt * 32 + ntg) * 32 + L];
                    } else if (augok) {
                        bw = WBau[ntg * 8 + Lq];
                    } else {
                        bw.x = 0ull; bw.y = 0ull;
                    }
                    mma16816(acc[g][nl], a0h, a1h, a2h, a3h, lo32(bw.x), hi32(bw.x));
                    mma16816(acc[g][nl], a0h, a1h, a2h, a3h, lo32(bw.y), hi32(bw.y));
                    mma16816(acc[g][nl], a0l, a1l, a2l, a3l, lo32(bw.x), hi32(bw.x));
                }
            }
        }
        __syncthreads();                     // all A/B reads done before rewrites

        // elementwise: this lane owns all 4 gates for 2 rows x 8 k-cols
        float hv[4][2][2];                   // [nl][s][q]
        #pragma unroll
        for (int nl = 0; nl < 4; nl++)
            #pragma unroll
            for (int s = 0; s < 2; s++)
                #pragma unroll
                for (int q = 0; q < 2; q++) {
                    int ci = s * 2 + q;
                    float zg = acc[0][nl][ci];
                    float zi = acc[1][nl][ci];
                    float zf = acc[2][nl][ci];
                    float zo = acc[3][nl][ci];
                    int cix = nl * 4 + ci;
                    float cv = fmaf(cst[cix], sig_a(zf), tanh_a(zg) * sig_a(zi));
                    cst[cix] = cv;
                    hv[nl][s][q] = tanh_a(cv) * sig_a(zo);
                }

        if (t == TT - 1) {
            #pragma unroll
            for (int nl = 0; nl < 4; nl++)
                #pragma unroll
                for (int s = 0; s < 2; s++)
                    #pragma unroll
                    for (int q = 0; q < 2; q++) {
                        int k = half * 32 + nl * 8 + (L & 3) * 2 + q;
                        hF[k * MROWS + r0 + s * 8] = hv[nl][s][q];
                    }
        } else {
            // write A fragments for t+1 (this warp owns kt = 2*half, 2*half+1)
            #pragma unroll
            for (int ktl = 0; ktl < 2; ktl++) {
                int kt = 2 * half + ktl;
                ull* aw = (ull*)&AH2[(mt * NKT + kt) * 32 + L];
                ull* al = (ull*)&AL2[(mt * NKT + kt) * 32 + L];
                #pragma unroll
                for (int s = 0; s < 2; s++) {
                    float e0 = hv[2 * ktl][s][0],     e1 = hv[2 * ktl][s][1];
                    float o0 = hv[2 * ktl + 1][s][0], o1 = hv[2 * ktl + 1][s][1];
                    uint32_t phE = pkbf(e0, e1), phO = pkbf(o0, o1);
                    aw[s] = (ull)phE | ((ull)phO << 32);
                    __nv_bfloat16 be0 = __float2bfloat16_rn(e0);
                    __nv_bfloat16 be1 = __float2bfloat16_rn(e1);
                    __nv_bfloat16 bo0 = __float2bfloat16_rn(o0);
                    __nv_bfloat16 bo1 = __float2bfloat16_rn(o1);
                    uint32_t plE = pkbf(e0 - __bfloat162float(be0), e1 - __bfloat162float(be1));
                    uint32_t plO = pkbf(o0 - __bfloat162float(bo0), o1 - __bfloat162float(bo1));
                    al[s] = (ull)plE | ((ull)plO << 32);
                }
            }
            if (half == 0 && (L & 3) == 0) {  // x_{t+1} augment
                ull* aw = (ull*)&AH2[(mt * NKT + 4) * 32 + L];
                ull* al = (ull*)&AL2[(mt * NKT + 4) * 32 + L];
                #pragma unroll
                for (int s = 0; s < 2; s++) {
                    float xv = xs[(r0 + s * 8) * TT + t + 1];
                    __nv_bfloat16 xh = __float2bfloat16_rn(xv);
                    aw[s] = (ull)((uint32_t)__bfloat16_as_ushort(xh) | (0x3F80u << 16));
                    al[s] = (ull)pkbf(xv - __bfloat162float(xh), 0.f);
                }
            }
        }
    }
    __syncthreads();

    // ---- load FC weights into overlay (A frags dead now) ----
    float* fc1s = (float*)(smc + SM_FC1);
    float* fc2s = (float*)(smc + SM_FC2);
    for (int i = tid; i < HH * 32; i += 256) fc1s[i] = fc1W[i];
    for (int i = tid; i < 32 * NOUT; i += 256) fc2s[i] = fc2W[i];
    __syncthreads();

    // ---- FC head: relu(h) -> 32 relu -> 12 ----
    #pragma unroll
    for (int rr = 0; rr < 8; rr++) {
        int row = w * 8 + rr;
        int n = n0 + row;
        float m = f1bs[L];
        #pragma unroll 8
        for (int j = 0; j < HH; j++)
            m = fmaf(fmaxf(hF[j * MROWS + row], 0.f), fc1s[j * 32 + L], m);
        m = fmaxf(m, 0.f);
        mids[w * 32 + L] = m;
        __syncwarp();
        if (L < NOUT) {
            float o = f2bs[L];
            #pragma unroll
            for (int q = 0; q < 32; q++)
                o = fmaf(mids[w * 32 + q], fc2s[q * NOUT + L], o);
            if (n < NN) out[(b * NOUT + L) * NN + n] = o;
        }
        __syncwarp();
    }
}

// ---------------- launch ----------------
extern "C" void kernel_launch(void* const* d_in, const int* in_sizes, int n_in,
                              void* d_out, int out_size) {
    const float* x      = (const float*)d_in[0];
    const float* lwx_W1 = (const float*)d_in[1];
    const float* lwx_b1 = (const float*)d_in[2];
    const float* lwx_W2 = (const float*)d_in[3];
    const float* lwx_b2 = (const float*)d_in[4];
    const float* lwh_W1 = (const float*)d_in[5];
    const float* lwh_b1 = (const float*)d_in[6];
    const float* lwh_W2 = (const float*)d_in[7];
    const float* lwh_b2 = (const float*)d_in[8];
    const float* lb_W1  = (const float*)d_in[9];
    const float* lb_b1  = (const float*)d_in[10];
    const float* lb_W2  = (const float*)d_in[11];
    const float* lb_b2  = (const float*)d_in[12];
    const float* fc1_W  = (const float*)d_in[13];
    const float* fc1_b  = (const float*)d_in[14];
    const float* fc2_W  = (const float*)d_in[15];
    const float* fc2_b  = (const float*)d_in[16];
    float* out = (float*)d_out;

    cudaFuncSetAttribute(k_lstm3, cudaFuncAttributeMaxDynamicSharedMemorySize, SM_TOT);

    k_meta<<<NB, EE>>>(x);
    k_hidden<<<dim3(NB, 4, 3), LHH>>>(lwx_W1, lwx_b1, lwh_W1, lwh_b1, lb_W1, lb_b1);
    k_small2<<<dim3(NB, 4, 2), HH>>>(lwx_W2, lwx_b2, lb_W2, lb_b2);
    k_wh2<<<dim3(8, 16, 4), 256>>>(lwh_W2, lwh_b2);
    k_pack3<<<dim3(NB, 4), 256>>>();
    k_packaug<<<NB, 256>>>();
    k_lstm3<<<dim3(NCHUNK, NB), 256, SM_TOT>>>(x, fc1_W, fc1_b, fc2_W, fc2_b, out);
}